// round 6
// baseline (speedup 1.0000x reference)
#include <cuda_runtime.h>

#define Bn  2
#define Cn  3
#define OCn 2
#define Hn  96
#define Wn  96
#define Nn  (Hn*Wn)        // 9216
#define NPER (Bn*Nn)       // 18432
#define NBLK 72

// Scratch (no device allocs allowed)
__device__ float g_Spart[18][4];   // per-(pair,chunk) dot partials, pre-scaled
__device__ float g_part[4][NBLK];  // BN stat partials: sum0,sum1,sq0,sq1
__device__ int   g_bar1 = 0, g_bar2 = 0, g_bar3 = 0;

__global__ void __launch_bounds__(256)
fused_all(const float* __restrict__ q, const float* __restrict__ k,
          const float* __restrict__ w, const float* __restrict__ bias,
          const float* __restrict__ gamma, const float* __restrict__ beta,
          float* __restrict__ out)
{
    const int t  = threadIdx.x;
    const int bk = blockIdx.x;
    const int lane = t & 31, warp = t >> 5;

    __shared__ float sm[8];
    __shared__ float sS[9];
    __shared__ float sW[54];
    __shared__ float red[4][8];
    __shared__ float sstat[4];

    // ---------------- Phase 1: partial dot products --------------------
    // 72 blocks = 18 (b,ch,c) pairs x 4 chunks of 576 float4 each.
    {
        const int pair  = bk >> 2;
        const int chunk = bk & 3;
        const int b   = pair / 9;
        const int rem = pair % 9;              // ch*3 + c
        const float4* kr = (const float4*)(k + (b*Cn + rem/3)*Nn);
        const float4* qr = (const float4*)(q + (b*Cn + rem%3)*Nn);
        const int base = chunk * 576;

        float acc = 0.f;
        #pragma unroll
        for (int j = 0; j < 3; j++) {
            const int i = j*256 + t;
            if (i < 576) {
                const float4 a  = kr[base + i];
                const float4 bb = qr[base + i];
                acc += a.x*bb.x + a.y*bb.y + a.z*bb.z + a.w*bb.w;
            }
        }
        #pragma unroll
        for (int o = 16; o; o >>= 1) acc += __shfl_down_sync(0xffffffffu, acc, o);
        if (lane == 0) sm[warp] = acc;
        __syncthreads();
        if (warp == 0) {
            acc = (lane < 8) ? sm[lane] : 0.f;
            #pragma unroll
            for (int o = 4; o; o >>= 1) acc += __shfl_down_sync(0xffffffffu, acc, o);
            if (lane == 0)
                g_Spart[pair][chunk] = acc * 0.57735026918962576451f; // 1/sqrt(3)
        }
    }

    // ---------------- Barrier 1 ----------------------------------------
    __threadfence();
    __syncthreads();
    if (t == 0) {
        atomicAdd(&g_bar1, 1);
        while (*(volatile int*)&g_bar1 < NBLK) { }
        __threadfence();
    }
    __syncthreads();

    // ---------------- Phase 2: fused conv + BN partials -----------------
    const int idx = bk * 256 + t;          // 0..18431
    const int b   = idx / Nn;
    const int n   = idx - b * Nn;
    const int yy  = n / Wn, xx = n - yy * Wn;

    if (t < 9)  sS[t] = g_Spart[b*9 + t][0] + g_Spart[b*9 + t][1]
                      + g_Spart[b*9 + t][2] + g_Spart[b*9 + t][3];
    if (t < 54) sW[t] = w[t];
    __syncthreads();

    float acc0 = bias[0];
    float acc1 = bias[1];

    #pragma unroll
    for (int ky = 0; ky < 3; ky++) {
        const int iy = yy + ky - 1;
        #pragma unroll
        for (int kx = 0; kx < 3; kx++) {
            const int ix = xx + kx - 1;
            if (iy >= 0 && iy < Hn && ix >= 0 && ix < Wn) {
                const int m = iy * Wn + ix;
                const float q0 = q[(b*Cn + 0)*Nn + m];
                const float q1 = q[(b*Cn + 1)*Nn + m];
                const float q2 = q[(b*Cn + 2)*Nn + m];
                const float a0 = q0*sS[0] + q1*sS[3] + q2*sS[6];   // sS[ch*3+c]
                const float a1 = q0*sS[1] + q1*sS[4] + q2*sS[7];
                const float a2 = q0*sS[2] + q1*sS[5] + q2*sS[8];
                const int kk = ky*3 + kx;
                acc0 += sW[0*9+kk]*a0 + sW[1*9+kk]*a1 + sW[2*9+kk]*a2;
                acc1 += sW[3*9+kk]*a0 + sW[4*9+kk]*a1 + sW[5*9+kk]*a2;
            }
        }
    }

    // block-reduce the 4 BN stat partials
    {
        float s0 = acc0, s1 = acc1, s2 = acc0*acc0, s3 = acc1*acc1;
        #pragma unroll
        for (int o = 16; o; o >>= 1) {
            s0 += __shfl_down_sync(0xffffffffu, s0, o);
            s1 += __shfl_down_sync(0xffffffffu, s1, o);
            s2 += __shfl_down_sync(0xffffffffu, s2, o);
            s3 += __shfl_down_sync(0xffffffffu, s3, o);
        }
        if (lane == 0) { red[0][warp]=s0; red[1][warp]=s1; red[2][warp]=s2; red[3][warp]=s3; }
        __syncthreads();
        if (t == 0) {
            float r0=0.f, r1=0.f, r2=0.f, r3=0.f;
            #pragma unroll
            for (int j = 0; j < 8; j++) { r0+=red[0][j]; r1+=red[1][j]; r2+=red[2][j]; r3+=red[3][j]; }
            g_part[0][bk]=r0; g_part[1][bk]=r1; g_part[2][bk]=r2; g_part[3][bk]=r3;
        }
    }

    // ---------------- Barrier 2 (last arriver resets bar1) ---------------
    __threadfence();
    __syncthreads();
    if (t == 0) {
        const int old = atomicAdd(&g_bar2, 1);
        if (old == NBLK-1) g_bar1 = 0;
        while (*(volatile int*)&g_bar2 < NBLK) { }
        __threadfence();
    }
    __syncthreads();

    // ---------------- Phase 3: final stats + BN + LeakyReLU --------------
    if (warp < 4) {
        float v = g_part[warp][lane] + g_part[warp][lane + 32]
                + ((lane < 8) ? g_part[warp][lane + 64] : 0.f);
        #pragma unroll
        for (int o = 16; o; o >>= 1) v += __shfl_down_sync(0xffffffffu, v, o);
        if (lane == 0) sstat[warp] = v;
    }
    __syncthreads();

    const float inv_n  = 1.0f / (float)NPER;
    const float mean0  = sstat[0] * inv_n;
    const float mean1  = sstat[1] * inv_n;
    const float var0   = sstat[2] * inv_n - mean0*mean0;
    const float var1   = sstat[3] * inv_n - mean1*mean1;
    const float sc0    = rsqrtf(var0 + 1e-5f) * gamma[0];
    const float sc1    = rsqrtf(var1 + 1e-5f) * gamma[1];
    const float b0     = beta[0], b1 = beta[1];

    float v0 = (acc0 - mean0) * sc0 + b0;
    float v1 = (acc1 - mean1) * sc1 + b1;
    out[(b*OCn + 0)*Nn + n] = (v0 >= 0.f) ? v0 : 0.1f*v0;
    out[(b*OCn + 1)*Nn + n] = (v1 >= 0.f) ? v1 : 0.1f*v1;

    // ---------------- Terminal: reset bar2/bar3 for next graph replay ----
    __threadfence();
    __syncthreads();
    if (t == 0) {
        const int old = atomicAdd(&g_bar3, 1);
        if (old == NBLK-1) { g_bar2 = 0; g_bar3 = 0; }
    }
}

// ---------------------------------------------------------------------------
extern "C" void kernel_launch(void* const* d_in, const int* in_sizes, int n_in,
                              void* d_out, int out_size)
{
    const float* q      = (const float*)d_in[0];  // X_tnext
    const float* k      = (const float*)d_in[1];  // X_hat_tnext
    const float* conv_w = (const float*)d_in[2];
    const float* conv_b = (const float*)d_in[3];
    const float* gamma  = (const float*)d_in[4];
    const float* beta   = (const float*)d_in[5];
    float* out = (float*)d_out;

    fused_all<<<NBLK, 256>>>(q, k, conv_w, conv_b, gamma, beta, out);
}

// round 7
// speedup vs baseline: 1.1875x; 1.1875x over previous
#include <cuda_runtime.h>

#define Bn  2
#define Cn  3
#define OCn 2
#define Hn  96
#define Wn  96
#define Nn  (Hn*Wn)        // 9216
#define NPER (Bn*Nn)       // 18432
#define NCTA 8             // one cluster
#define NT   768           // threads per CTA (24 warps)
#define NW   (NT/32)
#define ROWS 24            // image rows per CTA (4 CTAs per batch)

// Tiny cross-CTA scratch (overwritten every run; no counters -> replay-safe)
__device__ float g_Sp[NCTA][9];    // per-CTA dot partials (ch*3+c)
__device__ float g_bnp[NCTA][4];   // per-CTA BN partials: s0,s1,sq0,sq1

__device__ __forceinline__ float ldcv(const float* p) {
    float v;
    asm volatile("ld.global.cv.f32 %0, [%1];" : "=f"(v) : "l"(p));
    return v;
}

__global__ void __launch_bounds__(NT, 1) __cluster_dims__(NCTA, 1, 1)
fused_cluster(const float* __restrict__ q, const float* __restrict__ k,
              const float* __restrict__ w, const float* __restrict__ bias,
              const float* __restrict__ gamma, const float* __restrict__ beta,
              float* __restrict__ out)
{
    __shared__ __align__(16) float sq[Cn][ROWS+2][Wn];  // q tile + halo, ~30KB
    __shared__ float red[9][NW];
    __shared__ float sWp[OCn][Cn][9];                   // effective weights
    __shared__ float sstat[4];

    const int t    = threadIdx.x;
    const int bk   = blockIdx.x;
    const int lane = t & 31, warp = t >> 5;
    const int b    = bk >> 2;          // batch
    const int qd   = bk & 3;           // quarter
    const int r0   = qd * ROWS;        // first owned row
    const float* qb = q + b*Cn*Nn;
    const float* kb = k + b*Cn*Nn;

    // ---- Phase 1a: cooperative q-tile load (26 rows incl halo), float4 ----
    // 3ch * 26 rows * 24 float4 = 1872 float4
    for (int i = t; i < Cn*(ROWS+2)*24; i += NT) {
        const int col4 = i % 24;
        const int rr   = i / 24;            // ch*(ROWS+2)+trow
        const int ch   = rr / (ROWS+2);
        const int trow = rr % (ROWS+2);
        const int grow = r0 - 1 + trow;
        float4 v = make_float4(0.f, 0.f, 0.f, 0.f);
        if (grow >= 0 && grow < Hn)
            v = ((const float4*)(qb + ch*Nn + grow*Wn))[col4];
        ((float4*)&sq[ch][trow][0])[col4] = v;
    }

    // ---- Phase 1b: 9 dot partials over owned rows (576 float4 positions) ----
    float d[9];
    #pragma unroll
    for (int j = 0; j < 9; j++) d[j] = 0.f;
    if (t < 576) {
        const int base = (r0 * Wn) / 4 + t;   // float4 index in a channel plane
        float4 qq[3], kk[3];
        #pragma unroll
        for (int ch = 0; ch < 3; ch++) {
            qq[ch] = ((const float4*)(qb + ch*Nn))[base];
            kk[ch] = ((const float4*)(kb + ch*Nn))[base];
        }
        #pragma unroll
        for (int ch = 0; ch < 3; ch++)
            #pragma unroll
            for (int c = 0; c < 3; c++)
                d[ch*3+c] = kk[ch].x*qq[c].x + kk[ch].y*qq[c].y
                          + kk[ch].z*qq[c].z + kk[ch].w*qq[c].w;
    }
    #pragma unroll
    for (int j = 0; j < 9; j++) {
        float v = d[j];
        #pragma unroll
        for (int o = 16; o; o >>= 1) v += __shfl_down_sync(0xffffffffu, v, o);
        if (lane == 0) red[j][warp] = v;
    }
    __syncthreads();
    if (warp < 9) {
        float v = (lane < NW) ? red[warp][lane] : 0.f;
        #pragma unroll
        for (int o = 16; o; o >>= 1) v += __shfl_down_sync(0xffffffffu, v, o);
        if (lane == 0) g_Sp[bk][warp] = v;
    }

    // ---- Cluster barrier 1 (S partials visible to all CTAs) ----
    __threadfence();
    asm volatile("barrier.cluster.arrive.aligned;" ::: "memory");
    asm volatile("barrier.cluster.wait.aligned;"   ::: "memory");

    // ---- Phase 1c: S = sum of 4 quarter-partials; W'[o][ch] = sum_c S*w ----
    if (t < OCn*Cn*9) {                 // 54 threads
        const int o   = t / 27;
        const int rem = t % 27;
        const int ch  = rem / 9;
        const int kk  = rem % 9;
        float acc = 0.f;
        #pragma unroll
        for (int c = 0; c < 3; c++) {
            const int j = ch*3 + c;
            const float S = (ldcv(&g_Sp[b*4+0][j]) + ldcv(&g_Sp[b*4+1][j])
                           + ldcv(&g_Sp[b*4+2][j]) + ldcv(&g_Sp[b*4+3][j]))
                          * 0.57735026918962576451f;   // 1/sqrt(3)
            acc += S * w[(o*Cn + c)*9 + kk];
        }
        sWp[o][ch][kk] = acc;
    }
    __syncthreads();

    // ---- Phase 2: conv from smem tile; 3 contiguous pixels per thread ----
    const int row = t >> 5;            // 0..23 (owned row index)
    const int col = (t & 31) * 3;      // 0,3,...,93
    const float bias0 = bias[0], bias1 = bias[1];
    float y0[3] = {bias0, bias0, bias0};
    float y1[3] = {bias1, bias1, bias1};

    #pragma unroll
    for (int tr = 0; tr < 3; tr++) {
        const int trow = row + tr;     // tile row (halo offset already +1-1)
        #pragma unroll
        for (int ch = 0; ch < 3; ch++) {
            float v[5];
            v[0] = (col == 0)  ? 0.f : sq[ch][trow][col-1];
            v[1] = sq[ch][trow][col+0];
            v[2] = sq[ch][trow][col+1];
            v[3] = sq[ch][trow][col+2];
            v[4] = (col == 93) ? 0.f : sq[ch][trow][col+3];
            #pragma unroll
            for (int tc = 0; tc < 3; tc++) {
                const float w0 = sWp[0][ch][tr*3+tc];
                const float w1 = sWp[1][ch][tr*3+tc];
                #pragma unroll
                for (int j = 0; j < 3; j++) {
                    y0[j] += w0 * v[j+tc];
                    y1[j] += w1 * v[j+tc];
                }
            }
        }
    }

    // ---- Phase 2b: BN partial reduction (4 values over 24 warps) ----
    {
        float s0 = y0[0]+y0[1]+y0[2];
        float s1 = y1[0]+y1[1]+y1[2];
        float s2 = y0[0]*y0[0]+y0[1]*y0[1]+y0[2]*y0[2];
        float s3 = y1[0]*y1[0]+y1[1]*y1[1]+y1[2]*y1[2];
        #pragma unroll
        for (int o = 16; o; o >>= 1) {
            s0 += __shfl_down_sync(0xffffffffu, s0, o);
            s1 += __shfl_down_sync(0xffffffffu, s1, o);
            s2 += __shfl_down_sync(0xffffffffu, s2, o);
            s3 += __shfl_down_sync(0xffffffffu, s3, o);
        }
        if (lane == 0) { red[0][warp]=s0; red[1][warp]=s1; red[2][warp]=s2; red[3][warp]=s3; }
        __syncthreads();
        if (warp < 4) {
            float v = (lane < NW) ? red[warp][lane] : 0.f;
            #pragma unroll
            for (int o = 16; o; o >>= 1) v += __shfl_down_sync(0xffffffffu, v, o);
            if (lane == 0) g_bnp[bk][warp] = v;
        }
    }

    // ---- Cluster barrier 2 (BN partials visible) ----
    __threadfence();
    asm volatile("barrier.cluster.arrive.aligned;" ::: "memory");
    asm volatile("barrier.cluster.wait.aligned;"   ::: "memory");

    if (t < 4) {
        float v = 0.f;
        #pragma unroll
        for (int cta = 0; cta < NCTA; cta++) v += ldcv(&g_bnp[cta][t]);
        sstat[t] = v;
    }
    __syncthreads();

    // ---- Phase 3: BN (biased var, eps=1e-5) + affine + LeakyReLU(0.1) ----
    const float inv_n = 1.0f / (float)NPER;
    const float mean0 = sstat[0] * inv_n;
    const float mean1 = sstat[1] * inv_n;
    const float var0  = sstat[2] * inv_n - mean0*mean0;
    const float var1  = sstat[3] * inv_n - mean1*mean1;
    const float sc0   = rsqrtf(var0 + 1e-5f) * gamma[0];
    const float sc1   = rsqrtf(var1 + 1e-5f) * gamma[1];
    const float be0   = beta[0], be1 = beta[1];

    float* o0 = out + (b*OCn + 0)*Nn + (r0 + row)*Wn + col;
    float* o1 = out + (b*OCn + 1)*Nn + (r0 + row)*Wn + col;
    #pragma unroll
    for (int j = 0; j < 3; j++) {
        float v0 = (y0[j] - mean0) * sc0 + be0;
        float v1 = (y1[j] - mean1) * sc1 + be1;
        o0[j] = (v0 >= 0.f) ? v0 : 0.1f*v0;
        o1[j] = (v1 >= 0.f) ? v1 : 0.1f*v1;
    }
}

// ---------------------------------------------------------------------------
extern "C" void kernel_launch(void* const* d_in, const int* in_sizes, int n_in,
                              void* d_out, int out_size)
{
    const float* q      = (const float*)d_in[0];  // X_tnext
    const float* k      = (const float*)d_in[1];  // X_hat_tnext
    const float* conv_w = (const float*)d_in[2];
    const float* conv_b = (const float*)d_in[3];
    const float* gamma  = (const float*)d_in[4];
    const float* beta   = (const float*)d_in[5];
    float* out = (float*)d_out;

    fused_cluster<<<NCTA, NT>>>(q, k, conv_w, conv_b, gamma, beta, out);
}